// round 8
// baseline (speedup 1.0000x reference)
#include <cuda_runtime.h>
#include <cstdint>
#include <math.h>
#include <float.h>

// ---------------------------------------------------------------------------
// MultiBoxLoss (SSD) fused loss.  B=32, P=8732, C=81.
//   out[0] = loss_c / N, out[1] = loss_l / N
// cp.async double-buffered pipeline: each block streams 128-prior conf tiles
// (f32) into 2 smem stages via LDGSTS (no registers, deep in-flight queue)
// and computes per-prior nll from the previous stage.
// nll = lse - tgt_logit is both the CE term and the hard-negative rank key.
// Common case (num_neg >= #negatives): loss_c = sum of ALL nll.
// Rare case: exact top-k via radix select (tie-order invariant for a sum).
// ---------------------------------------------------------------------------

#define BATCH    32
#define PRIORS   8732
#define CLASSES  81
#define TPB      128
#define TILES_PER_BATCH ((PRIORS + TPB - 1) / TPB)  // 69
#define NTILES   (TILES_PER_BATCH * BATCH)          // 2208
#define GRID_MAIN 296                               // 2 blocks/SM on 148 SMs
#define TILE_ELEMS (TPB * CLASSES)                  // 10368 floats
#define SMEM_BYTES (2 * TILE_ELEMS * 4)             // 82,944 B
#define FULLMASK 0xFFFFFFFFu

// Device-global scratch; statically zero-init. The fused finalizer resets
// everything at the end of each call -> graph replays are deterministic.
__device__ double   g_sum_all[BATCH];
__device__ double   g_sum_pos[BATCH];
__device__ double   g_sum_loc[BATCH];
__device__ int      g_num_pos[BATCH];
__device__ int      g_flag64 = 1;          // 1 -> conf_t is int64
__device__ unsigned g_done   = 0;
__device__ float    g_vrank[BATCH * PRIORS];

// Detect int64 vs int32 labels reading ONLY the first 16384 int32 words
// (in-bounds under either layout). int64 labels in [0,81) -> odd words zero.
__global__ void k_detect(const int2* __restrict__ p) {
    int bad = 0;
    for (int i = blockIdx.x * blockDim.x + threadIdx.x; i < 8192;
         i += gridDim.x * blockDim.x)
        bad |= p[i].y;
    if (__syncthreads_or(bad) && threadIdx.x == 0) g_flag64 = 0;
}

__device__ __forceinline__ void cp16(uint32_t dst_smem, const void* src) {
    asm volatile("cp.async.cg.shared.global [%0], [%1], 16;"
                 :: "r"(dst_smem), "l"(src));
}
__device__ __forceinline__ void cp_commit() {
    asm volatile("cp.async.commit_group;");
}
__device__ __forceinline__ void cp_wait1() {
    asm volatile("cp.async.wait_group 1;");
}

// Issue async copy of tile i (global tile index) into stage buffer.
__device__ __forceinline__ void load_tile_async(
    const float* __restrict__ conf, uint32_t stage_smem, int i, int tid) {
    const int b  = i / TILES_PER_BATCH;
    const int tl = i % TILES_PER_BATCH;
    const int p0 = tl * TPB;
    const int np = min(TPB, PRIORS - p0);
    const long long g0 = (long long)b * PRIORS + p0;
    const float4* src4 = (const float4*)(conf + g0 * CLASSES);
    const int n4 = (np * CLASSES) >> 2;    // np*81 divisible by 4
    #pragma unroll 4
    for (int j = tid; j < n4; j += TPB)
        cp16(stage_smem + j * 16, src4 + j);
}

__global__ void __launch_bounds__(TPB)
k_main(const float* __restrict__ conf,
       const float4* __restrict__ loc,
       const void*  __restrict__ ct,
       const float4* __restrict__ loct,
       float* __restrict__ out, int out_size) {
    extern __shared__ __align__(16) float s_dyn[];   // [2][TILE_ELEMS]
    __shared__ float    s_f[4 * 3];
    __shared__ int      s_i[4];
    __shared__ unsigned s_last;
    __shared__ unsigned sh_prefix, sh_rare;
    __shared__ int      sh_k;
    __shared__ double   sh_lc, sh_ll;
    __shared__ long long sh_n;

    // finalizer scratch aliases stage 0 (only used after pipeline is done)
    double*   dred = (double*)s_dyn;               // 128 * 8B
    unsigned* hist = (unsigned*)(dred + TPB);      // 256 * 4B

    const int tid  = threadIdx.x;
    const int lane = tid & 31;
    const int wid  = tid >> 5;
    const int bid  = blockIdx.x;
    const int t0   = (bid * NTILES) / GRID_MAIN;
    const int t1   = ((bid + 1) * NTILES) / GRID_MAIN;   // nt = 7 or 8
    const bool is64 = (g_flag64 != 0);

    const uint32_t smem_base =
        (uint32_t)__cvta_generic_to_shared(s_dyn);
    const uint32_t stage_addr[2] = { smem_base, smem_base + TILE_ELEMS * 4 };

    // prefetch two tiles
    load_tile_async(conf, stage_addr[0], t0, tid);
    cp_commit();
    if (t0 + 1 < t1) load_tile_async(conf, stage_addr[1], t0 + 1, tid);
    cp_commit();

    float acc_all = 0.f, acc_pos = 0.f, acc_loc = 0.f;
    int   acc_cnt = 0, cur_b = -1;

    for (int i = t0; i < t1; i++) {
        const int s  = (i - t0) & 1;
        const int b  = i / TILES_PER_BATCH;
        const int tl = i % TILES_PER_BATCH;
        const int p0 = tl * TPB;
        const int np = min(TPB, PRIORS - p0);
        const long long g0 = (long long)b * PRIORS + p0;

        if (b != cur_b) {                          // flush previous batch
            if (cur_b >= 0) {
                float a = acc_all, pp = acc_pos, lcv = acc_loc; int nc = acc_cnt;
                #pragma unroll
                for (int o = 16; o > 0; o >>= 1) {
                    a  += __shfl_down_sync(FULLMASK, a,  o);
                    pp += __shfl_down_sync(FULLMASK, pp, o);
                    lcv+= __shfl_down_sync(FULLMASK, lcv,o);
                    nc += __shfl_down_sync(FULLMASK, nc, o);
                }
                if (lane == 0) { s_f[wid] = a; s_f[4+wid] = pp; s_f[8+wid] = lcv; s_i[wid] = nc; }
                __syncthreads();
                if (tid == 0) {
                    atomicAdd(&g_sum_all[cur_b], (double)(s_f[0]+s_f[1]+s_f[2]+s_f[3]));
                    atomicAdd(&g_sum_pos[cur_b], (double)(s_f[4]+s_f[5]+s_f[6]+s_f[7]));
                    atomicAdd(&g_sum_loc[cur_b], (double)(s_f[8]+s_f[9]+s_f[10]+s_f[11]));
                    atomicAdd(&g_num_pos[cur_b], s_i[0]+s_i[1]+s_i[2]+s_i[3]);
                }
                __syncthreads();
                acc_all = acc_pos = acc_loc = 0.f; acc_cnt = 0;
            }
            cur_b = b;
        }

        // label load (global; overlaps with async copies)
        int t = 0;
        const bool active = (tid < np);
        if (active) {
            t = is64 ? (int)((const long long*)ct)[g0 + tid]
                     : ((const int*)ct)[g0 + tid];
        }

        cp_wait1();             // copies for tile i are done (<=1 group pending)
        __syncthreads();        // all threads' copies for tile i are done

        if (active) {
            const float* r = s_dyn + (size_t)s * TILE_ELEMS + tid * CLASSES;
            float e0 = 0.f, e1 = 0.f, e2 = 0.f, e3 = 0.f;
            #pragma unroll
            for (int k = 0; k < 80; k += 4) {
                e0 += __expf(r[k]);     e1 += __expf(r[k + 1]);
                e2 += __expf(r[k + 2]); e3 += __expf(r[k + 3]);
            }
            const float sum = ((e0 + e1) + (e2 + e3)) + __expf(r[80]);
            const float nll = __logf(sum) - r[t];
            const bool  pos = (t > 0);
            g_vrank[g0 + tid] = pos ? 0.f : nll;
            acc_all += nll;
            if (pos) {
                acc_pos += nll; acc_cnt++;
                const float4 d4 = loc[g0 + tid], t4 = loct[g0 + tid];
                float dx = d4.x - t4.x, dy = d4.y - t4.y;
                float dz = d4.z - t4.z, dw = d4.w - t4.w;
                float ax = fabsf(dx), ay = fabsf(dy), az = fabsf(dz), aw = fabsf(dw);
                acc_loc += ((ax < 1.f) ? 0.5f * dx * dx : ax - 0.5f)
                         + ((ay < 1.f) ? 0.5f * dy * dy : ay - 0.5f)
                         + ((az < 1.f) ? 0.5f * dz * dz : az - 0.5f)
                         + ((aw < 1.f) ? 0.5f * dw * dw : aw - 0.5f);
            }
        }
        __syncthreads();        // everyone done reading stage s
        if (i + 2 < t1) load_tile_async(conf, stage_addr[s], i + 2, tid);
        cp_commit();            // commit (possibly empty) to keep groups aligned
    }

    // final flush
    if (cur_b >= 0) {
        float a = acc_all, pp = acc_pos, lcv = acc_loc; int nc = acc_cnt;
        #pragma unroll
        for (int o = 16; o > 0; o >>= 1) {
            a  += __shfl_down_sync(FULLMASK, a,  o);
            pp += __shfl_down_sync(FULLMASK, pp, o);
            lcv+= __shfl_down_sync(FULLMASK, lcv,o);
            nc += __shfl_down_sync(FULLMASK, nc, o);
        }
        if (lane == 0) { s_f[wid] = a; s_f[4+wid] = pp; s_f[8+wid] = lcv; s_i[wid] = nc; }
        __syncthreads();
        if (tid == 0) {
            atomicAdd(&g_sum_all[cur_b], (double)(s_f[0]+s_f[1]+s_f[2]+s_f[3]));
            atomicAdd(&g_sum_pos[cur_b], (double)(s_f[4]+s_f[5]+s_f[6]+s_f[7]));
            atomicAdd(&g_sum_loc[cur_b], (double)(s_f[8]+s_f[9]+s_f[10]+s_f[11]));
            atomicAdd(&g_num_pos[cur_b], s_i[0]+s_i[1]+s_i[2]+s_i[3]);
        }
    }

    __syncthreads();
    if (tid == 0) {
        __threadfence();
        s_last = atomicAdd(&g_done, 1u);
    }
    __syncthreads();
    if (s_last != (unsigned)(gridDim.x - 1)) return;

    // ======================= fused finalizer (last block) ===================
    __threadfence();
    if (tid < 32) {
        const int    npb  = ((volatile int*)g_num_pos)[tid];
        const double sall = ((volatile double*)g_sum_all)[tid];
        const double sloc = ((volatile double*)g_sum_loc)[tid];
        const long long nn = min((long long)3 * npb, (long long)(PRIORS - 1));
        const bool rare = (nn < (long long)(PRIORS - npb));
        const unsigned rm = __ballot_sync(FULLMASK, rare);
        double c = rare ? 0.0 : sall;
        double l = sloc;
        int    n = npb;
        #pragma unroll
        for (int o = 16; o > 0; o >>= 1) {
            c += __shfl_down_sync(FULLMASK, c, o);
            l += __shfl_down_sync(FULLMASK, l, o);
            n += __shfl_down_sync(FULLMASK, n, o);
        }
        if (tid == 0) { sh_lc = c; sh_ll = l; sh_n = n; sh_rare = rm; }
    }
    __syncthreads();

    double loss_c = sh_lc;
    unsigned rmask = sh_rare;
    // rare path: exact top-k radix select per flagged batch (expected none)
    while (rmask) {
        const int rb = __ffs(rmask) - 1;
        rmask &= rmask - 1;
        const int npb = ((volatile int*)g_num_pos)[rb];
        int kk = (int)min((long long)3 * npb, (long long)(PRIORS - 1));
        const float* v = g_vrank + (long long)rb * PRIORS;
        unsigned prefix = 0;
        for (int shift = 24; shift >= 0; shift -= 8) {
            for (int i = tid; i < 256; i += TPB) hist[i] = 0;
            __syncthreads();
            const unsigned mask_hi =
                (shift == 24) ? 0u : (0xFFFFFFFFu << (shift + 8));
            for (int i = tid; i < PRIORS; i += TPB) {
                const unsigned bits = __float_as_uint(v[i]);
                if ((bits & mask_hi) == prefix)
                    atomicAdd(&hist[(bits >> shift) & 255], 1u);
            }
            __syncthreads();
            if (tid == 0) {
                int acc = 0, bin = 255;
                for (; bin > 0; --bin) {
                    if (acc + (int)hist[bin] >= kk) break;
                    acc += (int)hist[bin];
                }
                sh_prefix = prefix | ((unsigned)bin << shift);
                sh_k      = kk - acc;
            }
            __syncthreads();
            prefix = sh_prefix; kk = sh_k;
            __syncthreads();
        }
        double local = 0.0;
        for (int i = tid; i < PRIORS; i += TPB) {
            const unsigned bits = __float_as_uint(v[i]);
            if (bits > prefix) local += (double)v[i];
        }
        dred[tid] = local;
        __syncthreads();
        for (int st = TPB / 2; st > 0; st >>= 1) {
            if (tid < st) dred[tid] += dred[tid + st];
            __syncthreads();
        }
        if (tid == 0) {
            loss_c += ((volatile double*)g_sum_pos)[rb] + dred[0] +
                      (double)kk * (double)__uint_as_float(prefix);
        }
        __syncthreads();
    }

    if (tid == 0) {
        const double N = (double)sh_n;
        if (out_size >= 1) out[0] = (float)(loss_c / N);
        if (out_size >= 2) out[1] = (float)(sh_ll / N);
    }

    // reset globals for the next graph replay
    if (tid < BATCH) {
        g_sum_all[tid] = 0.0; g_sum_pos[tid] = 0.0;
        g_sum_loc[tid] = 0.0; g_num_pos[tid] = 0;
    }
    if (tid == 0) { g_flag64 = 1; g_done = 0; }
}

extern "C" void kernel_launch(void* const* d_in, const int* in_sizes, int n_in,
                              void* d_out, int out_size) {
    const float*  conf = (const float*)d_in[0];
    const float4* loc  = (const float4*)d_in[1];
    const void*   ct   = d_in[2];
    const float4* loct = (const float4*)d_in[3];
    float*        out  = (float*)d_out;
    (void)in_sizes; (void)n_in;

    cudaFuncSetAttribute(k_main, cudaFuncAttributeMaxDynamicSharedMemorySize,
                         SMEM_BYTES);
    k_detect<<<8, 256>>>((const int2*)ct);
    k_main<<<GRID_MAIN, TPB, SMEM_BYTES>>>(conf, loc, ct, loct, out, out_size);
}

// round 9
// speedup vs baseline: 1.2045x; 1.2045x over previous
#include <cuda_runtime.h>
#include <cuda_fp16.h>
#include <cstdint>
#include <math.h>
#include <float.h>

// ---------------------------------------------------------------------------
// MultiBoxLoss (SSD) fused loss.  B=32, P=8732, C=81.
//   out[0] = loss_c / N, out[1] = loss_l / N
// Single-kernel design (best-benched structure): per-block fp16 smem staging
// of a 96-prior conf tile (coalesced float4 loads), thread-per-prior lse,
// in-block label-dtype self-detection, fused last-block finalizer.
// nll = lse - tgt_logit is both the CE term and the hard-negative rank key.
// Common case (num_neg >= #negatives): loss_c = sum of ALL nll.
// Rare case: exact top-k via radix select (tie-order invariant for a sum).
// ---------------------------------------------------------------------------

#define BATCH    32
#define PRIORS   8732
#define CLASSES  81
#define TPB      96                                // threads = priors per tile
#define NW       (TPB / 32)                        // 3 warps
#define TILES_PER_BATCH ((PRIORS + TPB - 1) / TPB) // 91
#define GRID_MAIN (TILES_PER_BATCH * BATCH)        // 2912
#define FULLMASK 0xFFFFFFFFu

// Device-global scratch; statically zero-init. The fused finalizer resets
// everything at the end of each call -> graph replays are deterministic.
__device__ double   g_sum_all[BATCH];
__device__ double   g_sum_pos[BATCH];
__device__ double   g_sum_loc[BATCH];
__device__ int      g_num_pos[BATCH];
__device__ unsigned g_done   = 0;
__device__ float    g_vrank[BATCH * PRIORS];

__global__ void __launch_bounds__(TPB, 14)
k_main(const float* __restrict__ conf,
       const float4* __restrict__ loc,
       const void*  __restrict__ ct,
       const float4* __restrict__ loct,
       float* __restrict__ out, int out_size) {
    __shared__ __align__(16) __half s_tile[TPB * CLASSES];   // 15,552 B
    __shared__ float    s_f[NW * 3];
    __shared__ int      s_i[NW];
    __shared__ unsigned s_last;
    __shared__ unsigned sh_prefix, sh_rare;
    __shared__ int      sh_k;
    __shared__ double   sh_lc, sh_ll;
    __shared__ long long sh_n;

    // Rare-path scratch aliases the tile (only used by the one last block,
    // after all tile reads, with __syncthreads() separating uses).
    double*   dred = (double*)s_tile;              // 128 * 8B  = [0, 1024)
    unsigned* hist = (unsigned*)s_tile + 256;      // 256 * 4B  = [1024, 2048)

    const int tid  = threadIdx.x;
    const int lane = tid & 31;
    const int wid  = tid >> 5;
    const int b    = blockIdx.x / TILES_PER_BATCH;
    const int tile = blockIdx.x % TILES_PER_BATCH;
    const int p0   = tile * TPB;
    const int np   = min(TPB, PRIORS - p0);

    // ---- label dtype self-detection: read first 64 int2 of ct (512 B,
    // in-bounds under either layout, L2-hot after the first block).
    // int64 labels in [0,81) -> all odd words zero. Under int32, 128 random
    // labels all-zero has p = (1/81)^128 ~ 0.
    int bad = 0;
    if (tid < 64) bad = ((const int2*)ct)[tid].y;
    const bool is64 = (__syncthreads_or(bad) == 0);

    const long long g0 = (long long)b * PRIORS + p0;

    // ---- stage conf tile: coalesced float4 loads, fp16 smem stores ----
    // (g0*81 divisible by 4 since 8732 and 96 are; np*81 divisible by 4)
    {
        const float4* src4 = (const float4*)(conf + g0 * CLASSES);
        __half2* dst2 = (__half2*)s_tile;
        const int n4 = (np * CLASSES) >> 2;
        #pragma unroll 4
        for (int i = tid; i < n4; i += TPB) {
            const float4 v = src4[i];
            dst2[2 * i]     = __floats2half2_rn(v.x, v.y);
            dst2[2 * i + 1] = __floats2half2_rn(v.z, v.w);
        }
    }

    // ---- label (overlaps with staging) ----
    const bool active = (tid < np);
    int t = 0;
    if (active) {
        t = is64 ? (int)((const long long*)ct)[g0 + tid]
                 : ((const int*)ct)[g0 + tid];
    }
    __syncthreads();

    float my_all = 0.f, my_pos = 0.f, my_loc = 0.f;
    int   my_cnt = 0;
    if (active) {
        const __half* r = s_tile + tid * CLASSES;
        float e0 = 0.f, e1 = 0.f, e2 = 0.f, e3 = 0.f;
        #pragma unroll
        for (int k = 0; k < 80; k += 4) {
            e0 += __expf(__half2float(r[k]));
            e1 += __expf(__half2float(r[k + 1]));
            e2 += __expf(__half2float(r[k + 2]));
            e3 += __expf(__half2float(r[k + 3]));
        }
        const float s   = ((e0 + e1) + (e2 + e3)) + __expf(__half2float(r[80]));
        const float nll = __logf(s) - __half2float(r[t]);
        const bool  pos = (t > 0);

        g_vrank[g0 + tid] = pos ? 0.f : nll;
        my_all = nll;
        if (pos) {
            my_pos = nll; my_cnt = 1;
            const float4 d4 = loc[g0 + tid], t4 = loct[g0 + tid];
            float dx = d4.x - t4.x, dy = d4.y - t4.y;
            float dz = d4.z - t4.z, dw = d4.w - t4.w;
            float ax = fabsf(dx), ay = fabsf(dy), az = fabsf(dz), aw = fabsf(dw);
            my_loc = ((ax < 1.f) ? 0.5f * dx * dx : ax - 0.5f)
                   + ((ay < 1.f) ? 0.5f * dy * dy : ay - 0.5f)
                   + ((az < 1.f) ? 0.5f * dz * dz : az - 0.5f)
                   + ((aw < 1.f) ? 0.5f * dw * dw : aw - 0.5f);
        }
    }

    // ---- block reduce (warp shfl, then NW leaders) ----
    #pragma unroll
    for (int o = 16; o > 0; o >>= 1) {
        my_all += __shfl_down_sync(FULLMASK, my_all, o);
        my_pos += __shfl_down_sync(FULLMASK, my_pos, o);
        my_loc += __shfl_down_sync(FULLMASK, my_loc, o);
        my_cnt += __shfl_down_sync(FULLMASK, my_cnt, o);
    }
    if (lane == 0) {
        s_f[wid] = my_all; s_f[NW + wid] = my_pos; s_f[2 * NW + wid] = my_loc;
        s_i[wid] = my_cnt;
    }
    __syncthreads();
    if (tid == 0) {
        float an = 0.f, pn = 0.f, lc = 0.f; int nc = 0;
        #pragma unroll
        for (int w = 0; w < NW; w++) {
            an += s_f[w]; pn += s_f[NW + w]; lc += s_f[2 * NW + w]; nc += s_i[w];
        }
        atomicAdd(&g_sum_all[b], (double)an);
        atomicAdd(&g_sum_pos[b], (double)pn);
        atomicAdd(&g_sum_loc[b], (double)lc);
        atomicAdd(&g_num_pos[b], nc);
        __threadfence();
        s_last = atomicAdd(&g_done, 1u);
    }
    __syncthreads();
    if (s_last != (unsigned)(gridDim.x - 1)) return;

    // ======================= fused finalizer (last block) ===================
    __threadfence();
    if (tid < 32) {
        const int    npb  = ((volatile int*)g_num_pos)[tid];
        const double sall = ((volatile double*)g_sum_all)[tid];
        const double sloc = ((volatile double*)g_sum_loc)[tid];
        const long long nn = min((long long)3 * npb, (long long)(PRIORS - 1));
        const bool rare = (nn < (long long)(PRIORS - npb));
        const unsigned rm = __ballot_sync(FULLMASK, rare);
        double c = rare ? 0.0 : sall;
        double l = sloc;
        int    n = npb;
        #pragma unroll
        for (int o = 16; o > 0; o >>= 1) {
            c += __shfl_down_sync(FULLMASK, c, o);
            l += __shfl_down_sync(FULLMASK, l, o);
            n += __shfl_down_sync(FULLMASK, n, o);
        }
        if (tid == 0) { sh_lc = c; sh_ll = l; sh_n = n; sh_rare = rm; }
    }
    __syncthreads();

    double loss_c = sh_lc;
    unsigned rmask = sh_rare;
    // rare path: exact top-k radix select per flagged batch (expected none)
    while (rmask) {
        const int rb = __ffs(rmask) - 1;
        rmask &= rmask - 1;
        const int npb = ((volatile int*)g_num_pos)[rb];
        int kk = (int)min((long long)3 * npb, (long long)(PRIORS - 1));
        const float* v = g_vrank + (long long)rb * PRIORS;
        unsigned prefix = 0;
        for (int shift = 24; shift >= 0; shift -= 8) {
            for (int i = tid; i < 256; i += TPB) hist[i] = 0;
            __syncthreads();
            const unsigned mask_hi =
                (shift == 24) ? 0u : (0xFFFFFFFFu << (shift + 8));
            for (int i = tid; i < PRIORS; i += TPB) {
                const unsigned bits = __float_as_uint(v[i]);
                if ((bits & mask_hi) == prefix)
                    atomicAdd(&hist[(bits >> shift) & 255], 1u);
            }
            __syncthreads();
            if (tid == 0) {
                int acc = 0, bin = 255;
                for (; bin > 0; --bin) {
                    if (acc + (int)hist[bin] >= kk) break;
                    acc += (int)hist[bin];
                }
                sh_prefix = prefix | ((unsigned)bin << shift);
                sh_k      = kk - acc;
            }
            __syncthreads();
            prefix = sh_prefix; kk = sh_k;
            __syncthreads();
        }
        double local = 0.0;
        for (int i = tid; i < PRIORS; i += TPB) {
            const unsigned bits = __float_as_uint(v[i]);
            if (bits > prefix) local += (double)v[i];
        }
        dred[tid] = local;
        if (tid < 128 - TPB) dred[TPB + tid] = 0.0;   // pad to 128 slots
        __syncthreads();
        for (int st = 64; st > 0; st >>= 1) {
            if (tid < st) dred[tid] += dred[tid + st];
            __syncthreads();
        }
        if (tid == 0) {
            loss_c += ((volatile double*)g_sum_pos)[rb] + dred[0] +
                      (double)kk * (double)__uint_as_float(prefix);
        }
        __syncthreads();
    }

    if (tid == 0) {
        const double N = (double)sh_n;
        if (out_size >= 1) out[0] = (float)(loss_c / N);
        if (out_size >= 2) out[1] = (float)(sh_ll / N);
    }

    // reset globals for the next graph replay
    if (tid < BATCH) {
        g_sum_all[tid] = 0.0; g_sum_pos[tid] = 0.0;
        g_sum_loc[tid] = 0.0; g_num_pos[tid] = 0;
    }
    if (tid == 0) g_done = 0;
}

extern "C" void kernel_launch(void* const* d_in, const int* in_sizes, int n_in,
                              void* d_out, int out_size) {
    const float*  conf = (const float*)d_in[0];
    const float4* loc  = (const float4*)d_in[1];
    const void*   ct   = d_in[2];
    const float4* loct = (const float4*)d_in[3];
    float*        out  = (float*)d_out;
    (void)in_sizes; (void)n_in;

    k_main<<<GRID_MAIN, TPB>>>(conf, loc, ct, loct, out, out_size);
}

// round 11
// speedup vs baseline: 1.2305x; 1.0216x over previous
#include <cuda_runtime.h>
#include <cuda_fp16.h>
#include <cstdint>
#include <math.h>
#include <float.h>

// ---------------------------------------------------------------------------
// MultiBoxLoss (SSD) fused loss.  B=32, P=8732, C=81.
//   out[0] = loss_c / N, out[1] = loss_l / N
// Single-kernel: per-block fp16 smem staging of a 96-prior conf tile
// (coalesced float4 loads, STS.64 packed stores), thread-per-prior lse read
// as aligned half2 windows, in-block label-dtype detection folded into the
// staging barrier, fused last-block finalizer.
// nll = lse - tgt_logit is both the CE term and the hard-negative rank key.
// Common case (num_neg >= #negatives): loss_c = sum of ALL nll.
// Rare case: exact top-k via radix select (tie-order invariant for a sum).
// ---------------------------------------------------------------------------

#define BATCH    32
#define PRIORS   8732
#define CLASSES  81
#define TPB      96                                // threads = priors per tile
#define NW       (TPB / 32)                        // 3 warps
#define TILES_PER_BATCH ((PRIORS + TPB - 1) / TPB) // 91
#define GRID_MAIN (TILES_PER_BATCH * BATCH)        // 2912
#define FULLMASK 0xFFFFFFFFu

// Device-global scratch; statically zero-init. The fused finalizer resets
// everything at the end of each call -> graph replays are deterministic.
__device__ double   g_sum_all[BATCH];
__device__ double   g_sum_pos[BATCH];
__device__ double   g_sum_loc[BATCH];
__device__ int      g_num_pos[BATCH];
__device__ unsigned g_done   = 0;
__device__ float    g_vrank[BATCH * PRIORS];

__global__ void __launch_bounds__(TPB, 14)
k_main(const float* __restrict__ conf,
       const float4* __restrict__ loc,
       const void*  __restrict__ ct,
       const float4* __restrict__ loct,
       float* __restrict__ out, int out_size) {
    __shared__ __align__(16) __half s_tile[TPB * CLASSES];   // 15,552 B
    __shared__ float    s_f[NW * 3];
    __shared__ int      s_i[NW];
    __shared__ unsigned s_last;
    __shared__ unsigned sh_prefix, sh_rare;
    __shared__ int      sh_k;
    __shared__ double   sh_lc, sh_ll;
    __shared__ long long sh_n;

    // Rare-path scratch aliases the tile (only the single last block uses it,
    // after all tile reads, with __syncthreads() separating uses).
    double*   dred = (double*)s_tile;              // 128 * 8B  = [0, 1024)
    unsigned* hist = (unsigned*)s_tile + 256;      // 256 * 4B  = [1024, 2048)

    const int tid  = threadIdx.x;
    const int lane = tid & 31;
    const int wid  = tid >> 5;
    const int b    = blockIdx.x / TILES_PER_BATCH;
    const int tile = blockIdx.x % TILES_PER_BATCH;
    const int p0   = tile * TPB;
    const int np   = min(TPB, PRIORS - p0);        // 96 or 92 (always even)
    const long long g0 = (long long)b * PRIORS + p0;

    // ---- stage conf tile FIRST: coalesced float4 loads, packed STS.64 ----
    {
        const float4* src4 = (const float4*)(conf + g0 * CLASSES);
        uint2* dst8 = (uint2*)s_tile;
        const int n4 = (np * CLASSES) >> 2;        // np*81 divisible by 4
        #pragma unroll 4
        for (int i = tid; i < n4; i += TPB) {
            const float4 v = src4[i];
            __half2 a = __floats2half2_rn(v.x, v.y);
            __half2 c = __floats2half2_rn(v.z, v.w);
            uint2 u;
            u.x = *reinterpret_cast<const uint32_t*>(&a);
            u.y = *reinterpret_cast<const uint32_t*>(&c);
            dst8[i] = u;
        }
    }

    // ---- label dtype detection (overlaps staging): first 64 int2 of ct
    // (512 B, in-bounds under either layout, L2-hot after block 0).
    // int64 labels in [0,81) -> all odd words zero; 128 random int32 labels
    // all-zero has p = (1/81)^128 ~ 0.
    int bad = 0;
    if (tid < 64) bad = ((const int2*)ct)[tid].y;
    // Single barrier: detect reduction AND staging-store visibility.
    const bool is64 = (__syncthreads_or(bad) == 0);

    const bool active = (tid < np);
    float my_all = 0.f, my_pos = 0.f, my_loc = 0.f;
    int   my_cnt = 0;

    if (active) {
        // label + loc loads issued up front; latency hides under the exps
        const int t = is64 ? (int)((const long long*)ct)[g0 + tid]
                           : ((const int*)ct)[g0 + tid];
        const float4 d4 = loc[g0 + tid];
        const float4 t4 = loct[g0 + tid];

        // Row p = tid starts at half index 81*tid (byte 162*tid, 2-mod-4 for
        // odd tid). Read the aligned 82-half window starting at
        // floor(81*tid/2) half2s and subtract the one stray exp:
        //   tid even: window = [row, row+82) -> stray = last .y
        //   tid odd : window = [row-1, row+81) -> stray = first .x
        // Window stays inside the staged np*81 halves for np in {96, 92}.
        const __half2* h2p = (const __half2*)s_tile + ((81 * tid) >> 1);
        float e0 = 0.f, e1 = 0.f, e2 = 0.f, e3 = 0.f;
        #pragma unroll
        for (int j = 0; j < 40; j += 4) {
            const float2 f0 = __half22float2(h2p[j]);
            const float2 f1 = __half22float2(h2p[j + 1]);
            const float2 f2 = __half22float2(h2p[j + 2]);
            const float2 f3 = __half22float2(h2p[j + 3]);
            e0 += __expf(f0.x) + __expf(f0.y);
            e1 += __expf(f1.x) + __expf(f1.y);
            e2 += __expf(f2.x) + __expf(f2.y);
            e3 += __expf(f3.x) + __expf(f3.y);
        }
        const float2 fl = __half22float2(h2p[40]);
        float sum = (((e0 + e1) + (e2 + e3)) + __expf(fl.x)) + __expf(fl.y);
        const float stray = (tid & 1) ? __half2float(__low2half(h2p[0]))
                                      : fl.y;
        sum -= __expf(stray);

        const float tv  = __half2float(s_tile[81 * tid + t]);
        const float nll = __logf(sum) - tv;
        const bool  pos = (t > 0);

        g_vrank[g0 + tid] = pos ? 0.f : nll;
        my_all = nll;
        if (pos) {
            my_pos = nll; my_cnt = 1;
            float dx = d4.x - t4.x, dy = d4.y - t4.y;
            float dz = d4.z - t4.z, dw = d4.w - t4.w;
            float ax = fabsf(dx), ay = fabsf(dy), az = fabsf(dz), aw = fabsf(dw);
            my_loc = ((ax < 1.f) ? 0.5f * dx * dx : ax - 0.5f)
                   + ((ay < 1.f) ? 0.5f * dy * dy : ay - 0.5f)
                   + ((az < 1.f) ? 0.5f * dz * dz : az - 0.5f)
                   + ((aw < 1.f) ? 0.5f * dw * dw : aw - 0.5f);
        }
    }

    // ---- block reduce (warp shfl, then NW leaders) ----
    #pragma unroll
    for (int o = 16; o > 0; o >>= 1) {
        my_all += __shfl_down_sync(FULLMASK, my_all, o);
        my_pos += __shfl_down_sync(FULLMASK, my_pos, o);
        my_loc += __shfl_down_sync(FULLMASK, my_loc, o);
        my_cnt += __shfl_down_sync(FULLMASK, my_cnt, o);
    }
    if (lane == 0) {
        s_f[wid] = my_all; s_f[NW + wid] = my_pos; s_f[2 * NW + wid] = my_loc;
        s_i[wid] = my_cnt;
    }
    __syncthreads();
    if (tid == 0) {
        float an = 0.f, pn = 0.f, lc = 0.f; int nc = 0;
        #pragma unroll
        for (int w = 0; w < NW; w++) {
            an += s_f[w]; pn += s_f[NW + w]; lc += s_f[2 * NW + w]; nc += s_i[w];
        }
        atomicAdd(&g_sum_all[b], (double)an);
        atomicAdd(&g_sum_pos[b], (double)pn);
        atomicAdd(&g_sum_loc[b], (double)lc);
        atomicAdd(&g_num_pos[b], nc);
        __threadfence();
        s_last = atomicAdd(&g_done, 1u);
    }
    __syncthreads();
    if (s_last != (unsigned)(gridDim.x - 1)) return;

    // ======================= fused finalizer (last block) ===================
    __threadfence();
    if (tid < 32) {
        const int    npb  = ((volatile int*)g_num_pos)[tid];
        const double sall = ((volatile double*)g_sum_all)[tid];
        const double sloc = ((volatile double*)g_sum_loc)[tid];
        const long long nn = min((long long)3 * npb, (long long)(PRIORS - 1));
        const bool rare = (nn < (long long)(PRIORS - npb));
        const unsigned rm = __ballot_sync(FULLMASK, rare);
        double c = rare ? 0.0 : sall;
        double l = sloc;
        int    n = npb;
        #pragma unroll
        for (int o = 16; o > 0; o >>= 1) {
            c += __shfl_down_sync(FULLMASK, c, o);
            l += __shfl_down_sync(FULLMASK, l, o);
            n += __shfl_down_sync(FULLMASK, n, o);
        }
        if (tid == 0) { sh_lc = c; sh_ll = l; sh_n = n; sh_rare = rm; }
    }
    __syncthreads();

    double loss_c = sh_lc;
    unsigned rmask = sh_rare;
    // rare path: exact top-k radix select per flagged batch (expected none)
    while (rmask) {
        const int rb = __ffs(rmask) - 1;
        rmask &= rmask - 1;
        const int npb = ((volatile int*)g_num_pos)[rb];
        int kk = (int)min((long long)3 * npb, (long long)(PRIORS - 1));
        const float* v = g_vrank + (long long)rb * PRIORS;
        unsigned prefix = 0;
        for (int shift = 24; shift >= 0; shift -= 8) {
            for (int i = tid; i < 256; i += TPB) hist[i] = 0;
            __syncthreads();
            const unsigned mask_hi =
                (shift == 24) ? 0u : (0xFFFFFFFFu << (shift + 8));
            for (int i = tid; i < PRIORS; i += TPB) {
                const unsigned bits = __float_as_uint(v[i]);
                if ((bits & mask_hi) == prefix)
                    atomicAdd(&hist[(bits >> shift) & 255], 1u);
            }
            __syncthreads();
            if (tid == 0) {
                int acc = 0, bin = 255;
                for (; bin > 0; --bin) {
                    if (acc + (int)hist[bin] >= kk) break;
                    acc += (int)hist[bin];
                }
                sh_prefix = prefix | ((unsigned)bin << shift);
                sh_k      = kk - acc;
            }
            __syncthreads();
            prefix = sh_prefix; kk = sh_k;
            __syncthreads();
        }
        double local = 0.0;
        for (int i = tid; i < PRIORS; i += TPB) {
            const unsigned bits = __float_as_uint(v[i]);
            if (bits > prefix) local += (double)v[i];
        }
        dred[tid] = local;
        if (tid < 128 - TPB) dred[TPB + tid] = 0.0;   // pad to 128 slots
        __syncthreads();
        for (int st = 64; st > 0; st >>= 1) {
            if (tid < st) dred[tid] += dred[tid + st];
            __syncthreads();
        }
        if (tid == 0) {
            loss_c += ((volatile double*)g_sum_pos)[rb] + dred[0] +
                      (double)kk * (double)__uint_as_float(prefix);
        }
        __syncthreads();
    }

    if (tid == 0) {
        const double N = (double)sh_n;
        if (out_size >= 1) out[0] = (float)(loss_c / N);
        if (out_size >= 2) out[1] = (float)(sh_ll / N);
    }

    // reset globals for the next graph replay
    if (tid < BATCH) {
        g_sum_all[tid] = 0.0; g_sum_pos[tid] = 0.0;
        g_sum_loc[tid] = 0.0; g_num_pos[tid] = 0;
    }
    if (tid == 0) g_done = 0;
}

extern "C" void kernel_launch(void* const* d_in, const int* in_sizes, int n_in,
                              void* d_out, int out_size) {
    const float*  conf = (const float*)d_in[0];
    const float4* loc  = (const float4*)d_in[1];
    const void*   ct   = d_in[2];
    const float4* loct = (const float4*)d_in[3];
    float*        out  = (float*)d_out;
    (void)in_sizes; (void)n_in;

    k_main<<<GRID_MAIN, TPB>>>(conf, loc, ct, loct, out, out_size);
}

// round 12
// speedup vs baseline: 1.3294x; 1.0804x over previous
#include <cuda_runtime.h>
#include <cuda_fp16.h>
#include <cstdint>
#include <math.h>
#include <float.h>

// ---------------------------------------------------------------------------
// MultiBoxLoss (SSD) fused loss.  B=32, P=8732, C=81.
//   out[0] = loss_c / N, out[1] = loss_l / N
// Warp-private tiles: each warp stages its own 32-prior conf slice to its own
// fp16 smem region (coalesced float4 loads, packed STS.64) and syncs with
// __syncwarp() only -- no block barrier in the hot path, so the 42 warps/SM
// self-stagger their load phases instead of convoying block-wise.
// nll = lse - tgt_logit is both the CE term and the hard-negative rank key.
// Common case (num_neg >= #negatives): loss_c = sum of ALL nll.
// Rare case: exact top-k via radix select (tie-order invariant for a sum).
// ---------------------------------------------------------------------------

#define BATCH    32
#define PRIORS   8732
#define CLASSES  81
#define TPB      96                                // 3 warps, 1 prior/thread
#define NW       (TPB / 32)
#define WROWS    32                                // priors per warp slice
#define WHALF    (WROWS * CLASSES)                 // 2592 halves per slice
#define TILES_PER_BATCH ((PRIORS + TPB - 1) / TPB) // 91
#define GRID_MAIN (TILES_PER_BATCH * BATCH)        // 2912
#define FULLMASK 0xFFFFFFFFu

// Device-global scratch; statically zero-init. The fused finalizer resets
// everything at the end of each call -> graph replays are deterministic.
__device__ double   g_sum_all[BATCH];
__device__ double   g_sum_pos[BATCH];
__device__ double   g_sum_loc[BATCH];
__device__ int      g_num_pos[BATCH];
__device__ unsigned g_done   = 0;
__device__ float    g_vrank[BATCH * PRIORS];

__global__ void __launch_bounds__(TPB, 14)
k_main(const float* __restrict__ conf,
       const float4* __restrict__ loc,
       const void*  __restrict__ ct,
       const float4* __restrict__ loct,
       float* __restrict__ out, int out_size) {
    __shared__ __align__(16) __half s_tile[NW][WHALF];   // 3 x 5184 B
    __shared__ float    s_f[NW * 3];
    __shared__ int      s_i[NW];
    __shared__ unsigned s_last;
    __shared__ unsigned sh_prefix, sh_rare;
    __shared__ int      sh_k;
    __shared__ double   sh_lc, sh_ll;
    __shared__ long long sh_n;

    // Rare-path scratch aliases the tile (only the single last block uses it,
    // after all tile reads, with __syncthreads() separating uses).
    double*   dred = (double*)&s_tile[0][0];       // 128 * 8B
    unsigned* hist = (unsigned*)&s_tile[0][0] + 256;

    const int tid  = threadIdx.x;
    const int lane = tid & 31;
    const int wid  = tid >> 5;
    const int b    = blockIdx.x / TILES_PER_BATCH;
    const int tile = blockIdx.x % TILES_PER_BATCH;
    const int p0   = tile * TPB;
    const int np   = min(TPB, PRIORS - p0);        // 96 or 92
    const long long g0 = (long long)b * PRIORS + p0;

    // ---- per-warp label-dtype detection: 32 int2 (256 B, L2-hot).
    // int64 labels in [0,81) -> odd words all zero; 32 random int32 labels
    // all-zero has p = (1/81)^32 ~ 1e-61.
    const int  bad  = ((const int2*)ct)[lane].y;
    const bool is64 = !__any_sync(FULLMASK, bad);

    // ---- stage this warp's slice: coalesced float4 loads, packed STS.64 ----
    const int       w0    = wid * WROWS;                   // first local row
    const int       nrows = min(WROWS, np - w0);           // 32 or 28
    const long long gw    = g0 + w0;                       // gw*81 % 4 == 0
    {
        const float4* src4 = (const float4*)(conf + gw * CLASSES);
        uint2* dst8 = (uint2*)&s_tile[wid][0];
        const int n4 = (nrows * CLASSES) >> 2;             // div by 4
        #pragma unroll 4
        for (int j = lane; j < n4; j += 32) {
            const float4 v = src4[j];
            __half2 a = __floats2half2_rn(v.x, v.y);
            __half2 c = __floats2half2_rn(v.z, v.w);
            uint2 u;
            u.x = *reinterpret_cast<const uint32_t*>(&a);
            u.y = *reinterpret_cast<const uint32_t*>(&c);
            dst8[j] = u;
        }
    }
    __syncwarp();          // warp-scope: staging visible to this warp only

    const bool active = (lane < nrows);
    float my_all = 0.f, my_pos = 0.f, my_loc = 0.f;
    int   my_cnt = 0;

    if (active) {
        // label + loc loads issued up front; latency hides under the exps
        const int t = is64 ? (int)((const long long*)ct)[gw + lane]
                           : ((const int*)ct)[gw + lane];
        const float4 d4 = loc[gw + lane];
        const float4 t4 = loct[gw + lane];

        // Row L = lane starts at half index 81*L in the slice. Read the
        // aligned 82-half window starting at half2 floor(81*L/2), subtract
        // the one stray exp (even L: trailing .y; odd L: leading .x).
        // Windows stay inside the staged nrows*81 halves for nrows in {32,28}.
        const __half2* h2p = (const __half2*)&s_tile[wid][0] + ((81 * lane) >> 1);
        float e0 = 0.f, e1 = 0.f, e2 = 0.f, e3 = 0.f;
        #pragma unroll
        for (int j = 0; j < 40; j += 4) {
            const float2 f0 = __half22float2(h2p[j]);
            const float2 f1 = __half22float2(h2p[j + 1]);
            const float2 f2 = __half22float2(h2p[j + 2]);
            const float2 f3 = __half22float2(h2p[j + 3]);
            e0 += __expf(f0.x) + __expf(f0.y);
            e1 += __expf(f1.x) + __expf(f1.y);
            e2 += __expf(f2.x) + __expf(f2.y);
            e3 += __expf(f3.x) + __expf(f3.y);
        }
        const float2 fl = __half22float2(h2p[40]);
        float sum = (((e0 + e1) + (e2 + e3)) + __expf(fl.x)) + __expf(fl.y);
        const float stray = (lane & 1) ? __half2float(__low2half(h2p[0]))
                                       : fl.y;
        sum -= __expf(stray);

        const float tv  = __half2float(s_tile[wid][81 * lane + t]);
        const float nll = __logf(sum) - tv;
        const bool  pos = (t > 0);

        g_vrank[gw + lane] = pos ? 0.f : nll;
        my_all = nll;
        if (pos) {
            my_pos = nll; my_cnt = 1;
            float dx = d4.x - t4.x, dy = d4.y - t4.y;
            float dz = d4.z - t4.z, dw = d4.w - t4.w;
            float ax = fabsf(dx), ay = fabsf(dy), az = fabsf(dz), aw = fabsf(dw);
            my_loc = ((ax < 1.f) ? 0.5f * dx * dx : ax - 0.5f)
                   + ((ay < 1.f) ? 0.5f * dy * dy : ay - 0.5f)
                   + ((az < 1.f) ? 0.5f * dz * dz : az - 0.5f)
                   + ((aw < 1.f) ? 0.5f * dw * dw : aw - 0.5f);
        }
    }

    // ---- block reduce (warp shfl, then NW leaders; first block barrier) ----
    #pragma unroll
    for (int o = 16; o > 0; o >>= 1) {
        my_all += __shfl_down_sync(FULLMASK, my_all, o);
        my_pos += __shfl_down_sync(FULLMASK, my_pos, o);
        my_loc += __shfl_down_sync(FULLMASK, my_loc, o);
        my_cnt += __shfl_down_sync(FULLMASK, my_cnt, o);
    }
    if (lane == 0) {
        s_f[wid] = my_all; s_f[NW + wid] = my_pos; s_f[2 * NW + wid] = my_loc;
        s_i[wid] = my_cnt;
    }
    __syncthreads();
    if (tid == 0) {
        float an = 0.f, pn = 0.f, lc = 0.f; int nc = 0;
        #pragma unroll
        for (int w = 0; w < NW; w++) {
            an += s_f[w]; pn += s_f[NW + w]; lc += s_f[2 * NW + w]; nc += s_i[w];
        }
        atomicAdd(&g_sum_all[b], (double)an);
        atomicAdd(&g_sum_pos[b], (double)pn);
        atomicAdd(&g_sum_loc[b], (double)lc);
        atomicAdd(&g_num_pos[b], nc);
        __threadfence();
        s_last = atomicAdd(&g_done, 1u);
    }
    __syncthreads();
    if (s_last != (unsigned)(gridDim.x - 1)) return;

    // ======================= fused finalizer (last block) ===================
    __threadfence();
    if (tid < 32) {
        const int    npb  = ((volatile int*)g_num_pos)[tid];
        const double sall = ((volatile double*)g_sum_all)[tid];
        const double sloc = ((volatile double*)g_sum_loc)[tid];
        const long long nn = min((long long)3 * npb, (long long)(PRIORS - 1));
        const bool rare = (nn < (long long)(PRIORS - npb));
        const unsigned rm = __ballot_sync(FULLMASK, rare);
        double c = rare ? 0.0 : sall;
        double l = sloc;
        int    n = npb;
        #pragma unroll
        for (int o = 16; o > 0; o >>= 1) {
            c += __shfl_down_sync(FULLMASK, c, o);
            l += __shfl_down_sync(FULLMASK, l, o);
            n += __shfl_down_sync(FULLMASK, n, o);
        }
        if (tid == 0) { sh_lc = c; sh_ll = l; sh_n = n; sh_rare = rm; }
    }
    __syncthreads();

    double loss_c = sh_lc;
    unsigned rmask = sh_rare;
    // rare path: exact top-k radix select per flagged batch (expected none)
    while (rmask) {
        const int rb = __ffs(rmask) - 1;
        rmask &= rmask - 1;
        const int npb = ((volatile int*)g_num_pos)[rb];
        int kk = (int)min((long long)3 * npb, (long long)(PRIORS - 1));
        const float* v = g_vrank + (long long)rb * PRIORS;
        unsigned prefix = 0;
        for (int shift = 24; shift >= 0; shift -= 8) {
            for (int i = tid; i < 256; i += TPB) hist[i] = 0;
            __syncthreads();
            const unsigned mask_hi =
                (shift == 24) ? 0u : (0xFFFFFFFFu << (shift + 8));
            for (int i = tid; i < PRIORS; i += TPB) {
                const unsigned bits = __float_as_uint(v[i]);
                if ((bits & mask_hi) == prefix)
                    atomicAdd(&hist[(bits >> shift) & 255], 1u);
            }
            __syncthreads();
            if (tid == 0) {
                int acc = 0, bin = 255;
                for (; bin > 0; --bin) {
                    if (acc + (int)hist[bin] >= kk) break;
                    acc += (int)hist[bin];
                }
                sh_prefix = prefix | ((unsigned)bin << shift);
                sh_k      = kk - acc;
            }
            __syncthreads();
            prefix = sh_prefix; kk = sh_k;
            __syncthreads();
        }
        double local = 0.0;
        for (int i = tid; i < PRIORS; i += TPB) {
            const unsigned bits = __float_as_uint(v[i]);
            if (bits > prefix) local += (double)v[i];
        }
        dred[tid] = local;
        if (tid < 128 - TPB) dred[TPB + tid] = 0.0;   // pad to 128 slots
        __syncthreads();
        for (int st = 64; st > 0; st >>= 1) {
            if (tid < st) dred[tid] += dred[tid + st];
            __syncthreads();
        }
        if (tid == 0) {
            loss_c += ((volatile double*)g_sum_pos)[rb] + dred[0] +
                      (double)kk * (double)__uint_as_float(prefix);
        }
        __syncthreads();
    }

    if (tid == 0) {
        const double N = (double)sh_n;
        if (out_size >= 1) out[0] = (float)(loss_c / N);
        if (out_size >= 2) out[1] = (float)(sh_ll / N);
    }

    // reset globals for the next graph replay
    if (tid < BATCH) {
        g_sum_all[tid] = 0.0; g_sum_pos[tid] = 0.0;
        g_sum_loc[tid] = 0.0; g_num_pos[tid] = 0;
    }
    if (tid == 0) g_done = 0;
}

extern "C" void kernel_launch(void* const* d_in, const int* in_sizes, int n_in,
                              void* d_out, int out_size) {
    const float*  conf = (const float*)d_in[0];
    const float4* loc  = (const float4*)d_in[1];
    const void*   ct   = d_in[2];
    const float4* loct = (const float4*)d_in[3];
    float*        out  = (float*)d_out;
    (void)in_sizes; (void)n_in;

    k_main<<<GRID_MAIN, TPB>>>(conf, loc, ct, loct, out, out_size);
}